// round 16
// baseline (speedup 1.0000x reference)
#include <cuda_runtime.h>
#include <cuda_fp16.h>

#define NN 100000
#define EE 1600000
#define DH 128
#define NH 8
#define MAXDEG 64   // in-degree ~ Poisson(16); P(max over 100k nodes >= 64) ~ 1e-14

// ---------------- scratch (device globals; no allocs allowed) ----------------
__device__ __half g_KVh[(size_t)NN * 256];      // 51.2 MB: row = 128 K halves + 128 V halves
__device__ __half g_aggh[(size_t)NN * DH];      // 25.6 MB (fp16 normalized attention out)
__device__ int    g_cnt[NN];                    // in-degree per node
__device__ int    g_esrc[(size_t)NN * MAXDEG];  // ELL: src list per dst, stride 64 (25.6 MB)

// ---------------- init ----------------
__global__ void init_kernel() {
    int i = blockIdx.x * blockDim.x + threadIdx.x;
    if (i < NN) g_cnt[i] = 0;
}

// ---------------- fused count + scatter (single edge pass, ELL layout) ----------------
__global__ __launch_bounds__(256)
void count_scatter_kernel(const int* __restrict__ ei) {
    int e = blockIdx.x * blockDim.x + threadIdx.x;
    if (e >= EE) return;
    int src = ei[e];
    int dst = ei[EE + e];
    int r = atomicAdd(&g_cnt[dst], 1);
    if (r < MAXDEG) g_esrc[(size_t)dst * MAXDEG + r] = src;
}

__device__ __forceinline__ unsigned packh2(float x, float y) {
    __half2 h = __floats2half2_rn(x, y);
    return *(unsigned*)&h;
}

// ---------------- A-resident fp16 GEMM ----------------
// Full 128x128 A tile loaded ONCE into smem (fp16, row stride 68 uints ->
// fragment-load bank = (4*lr+lc)%32, conflict-free), then up to two B-phases:
//   phase p: C_p = A @ B_p^T + bias_p  via mma.sync.m16n8k16.f16 (fp32 accum).
// 256 threads = 8 warps (4m x 2n), warp tile 32x64; B double-buffered per k16
// chunk. B1 == nullptr -> single phase. C row stride = cstride elements
// (256 for the interleaved KV buffer, 128 for plain out).
template <typename IT, typename OT>
__global__ __launch_bounds__(256)
void gemm_fused(const IT* __restrict__ A, int M, int cstride,
                const float* __restrict__ B0, const float* __restrict__ bias0, OT* __restrict__ C0,
                const float* __restrict__ B1, const float* __restrict__ bias1, OT* __restrict__ C1)
{
    __shared__ unsigned Asm[128][68];
    __shared__ unsigned Bsm[2][128][12];

    const int tid  = threadIdx.x;
    const int lane = tid & 31;
    const int wid  = tid >> 5;
    const int mBase = (wid & 3) * 32;
    const int nBase = (wid >> 2) * 64;
    const int rowBase = blockIdx.x * 128;
    const int lr = lane >> 2;
    const int lc = lane & 3;

    // ---- load full A tile into smem (once) ----
    if constexpr (sizeof(IT) == 4) {
#pragma unroll
        for (int b = 0; b < 2; b++) {
            float4 tmp[8];
#pragma unroll
            for (int j = 0; j < 8; j++) {
                int idx = (b * 8 + j) * 256 + tid;
                int row = idx >> 5, qq = idx & 31;
                int grow = rowBase + row;
                tmp[j] = (grow < M) ? *(const float4*)&A[(size_t)grow * 128 + qq * 4]
                                    : make_float4(0.f, 0.f, 0.f, 0.f);
            }
#pragma unroll
            for (int j = 0; j < 8; j++) {
                int idx = (b * 8 + j) * 256 + tid;
                int row = idx >> 5, qq = idx & 31;
                Asm[row][qq * 2]     = packh2(tmp[j].x, tmp[j].y);
                Asm[row][qq * 2 + 1] = packh2(tmp[j].z, tmp[j].w);
            }
        }
    } else {
        uint4 tmp[8];
#pragma unroll
        for (int j = 0; j < 8; j++) {
            int idx = j * 256 + tid;
            int row = idx >> 4, qq = idx & 15;
            int grow = rowBase + row;
            tmp[j] = (grow < M) ? *(const uint4*)&A[(size_t)grow * 128 + qq * 8]
                                : make_uint4(0u, 0u, 0u, 0u);
        }
#pragma unroll
        for (int j = 0; j < 8; j++) {
            int idx = j * 256 + tid;
            int row = idx >> 4, qq = idx & 15;
            Asm[row][qq * 4]     = tmp[j].x;
            Asm[row][qq * 4 + 1] = tmp[j].y;
            Asm[row][qq * 4 + 2] = tmp[j].z;
            Asm[row][qq * 4 + 3] = tmp[j].w;
        }
    }

    float4 pb[2];
    auto loadB = [&](const float* __restrict__ B, int s) {
#pragma unroll
        for (int r = 0; r < 2; r++) {
            int i = tid + r * 256;
            int row = i >> 2;
            int kq = i & 3;
            pb[r] = *(const float4*)&B[(size_t)row * 128 + s * 16 + kq * 4];
        }
    };
    auto storeB = [&](int buf) {
#pragma unroll
        for (int r = 0; r < 2; r++) {
            int i = tid + r * 256;
            int row = i >> 2;
            int c0 = (i & 3) * 2;
            Bsm[buf][row][c0]     = packh2(pb[r].x, pb[r].y);
            Bsm[buf][row][c0 + 1] = packh2(pb[r].z, pb[r].w);
        }
    };

#pragma unroll
    for (int p = 0; p < 2; p++) {
        const float* __restrict__ B    = p ? B1 : B0;
        if (B == nullptr) break;
        const float* __restrict__ bias = p ? bias1 : bias0;
        OT* __restrict__ C             = p ? C1 : C0;

        float acc[2][8][4];
#pragma unroll
        for (int mt = 0; mt < 2; mt++)
#pragma unroll
            for (int nt = 0; nt < 8; nt++)
#pragma unroll
                for (int r = 0; r < 4; r++) acc[mt][nt][r] = 0.0f;

        loadB(B, 0);
        __syncthreads();
        storeB(0);
        __syncthreads();

        for (int s = 0; s < 8; s++) {
            int buf = s & 1;
            if (s < 7) loadB(B, s + 1);

            unsigned af[2][4];
#pragma unroll
            for (int mt = 0; mt < 2; mt++) {
                int r0 = mBase + mt * 16 + lr;
                af[mt][0] = Asm[r0][s * 8 + lc];
                af[mt][1] = Asm[r0 + 8][s * 8 + lc];
                af[mt][2] = Asm[r0][s * 8 + lc + 4];
                af[mt][3] = Asm[r0 + 8][s * 8 + lc + 4];
            }
            unsigned bf[8][2];
#pragma unroll
            for (int nt = 0; nt < 8; nt++) {
                int nr = nBase + nt * 8 + lr;
                bf[nt][0] = Bsm[buf][nr][lc];
                bf[nt][1] = Bsm[buf][nr][lc + 4];
            }
#pragma unroll
            for (int mt = 0; mt < 2; mt++)
#pragma unroll
                for (int nt = 0; nt < 8; nt++) {
                    asm volatile(
                        "mma.sync.aligned.m16n8k16.row.col.f32.f16.f16.f32 "
                        "{%0,%1,%2,%3}, {%4,%5,%6,%7}, {%8,%9}, {%0,%1,%2,%3};"
                        : "+f"(acc[mt][nt][0]), "+f"(acc[mt][nt][1]),
                          "+f"(acc[mt][nt][2]), "+f"(acc[mt][nt][3])
                        : "r"(af[mt][0]), "r"(af[mt][1]), "r"(af[mt][2]), "r"(af[mt][3]),
                          "r"(bf[nt][0]), "r"(bf[nt][1]));
                }

            if (s < 7) {
                __syncthreads();
                storeB((s + 1) & 1);
                __syncthreads();
            }
        }

#pragma unroll
        for (int nt = 0; nt < 8; nt++) {
            int col = nBase + nt * 8 + lc * 2;
            float b0 = bias[col], b1 = bias[col + 1];
#pragma unroll
            for (int mt = 0; mt < 2; mt++) {
                int row0 = rowBase + mBase + mt * 16 + lr;
                if (row0 < M) {
                    if constexpr (sizeof(OT) == 2) {
                        __half2 h = __floats2half2_rn(acc[mt][nt][0] + b0, acc[mt][nt][1] + b1);
                        *(__half2*)&C[(size_t)row0 * cstride + col] = h;
                    } else {
                        float2 o = {acc[mt][nt][0] + b0, acc[mt][nt][1] + b1};
                        *(float2*)&C[(size_t)row0 * cstride + col] = o;
                    }
                }
                int row1 = row0 + 8;
                if (row1 < M) {
                    if constexpr (sizeof(OT) == 2) {
                        __half2 h = __floats2half2_rn(acc[mt][nt][2] + b0, acc[mt][nt][3] + b1);
                        *(__half2*)&C[(size_t)row1 * cstride + col] = h;
                    } else {
                        float2 o = {acc[mt][nt][2] + b0, acc[mt][nt][3] + b1};
                        *(float2*)&C[(size_t)row1 * cstride + col] = o;
                    }
                }
            }
        }
    }
}

// ---------------- per-node aggregation (ELL, 2 edges per warp-iteration) ----------------
// One warp per destination node. Lane l covers 8 dims [8*sub, 8*sub+8) of
// edge (i + e), where sub = l&15, e = l>>4 -> the warp processes TWO edges
// per iteration. Head = 16 dims = 2 lanes -> dot-reduce is a single shuffle.
// Dot in half2 (4 HFMA2); exp/sumex per lane; V accumulated in fp32.
// At the end the two edge-subsets (e=0 / e=1) are combined via xor-16
// shuffles, then lanes 0..15 write the normalized fp16 row.
__global__ __launch_bounds__(256)
void node_agg_kernel(const float* __restrict__ q) {
    int node = blockIdx.x * 8 + (threadIdx.x >> 5);
    int lane = threadIdx.x & 31;
    if (node >= NN) return;

    int deg = g_cnt[node];
    if (deg > MAXDEG) deg = MAXDEG;

    const uint4* KV4 = (const uint4*)g_KVh;     // row = 32 uint4: K at 0..15, V at 16..31
    const int* idx1 = &g_esrc[(size_t)node * MAXDEG];

    const int sub = lane & 15;
    const int e   = lane >> 4;

    // q dims [8*sub, 8*sub+8) as 4 half2 (converted once per node)
    float4 qa = *(const float4*)&q[(size_t)node * 128 + sub * 8];
    float4 qb = *(const float4*)&q[(size_t)node * 128 + sub * 8 + 4];
    __half2 qh0 = __floats2half2_rn(qa.x, qa.y);
    __half2 qh1 = __floats2half2_rn(qa.z, qa.w);
    __half2 qh2 = __floats2half2_rn(qb.x, qb.y);
    __half2 qh3 = __floats2half2_rn(qb.z, qb.w);

    float a[8];
#pragma unroll
    for (int j = 0; j < 8; j++) a[j] = 0.f;
    float sumex = 0.f;

    // process edges (sx, sy); nvalid = 2 normally, 1 for an odd tail
    auto step2 = [&](int sx, int sy, int nvalid) {
        bool valid = (e < nvalid);
        int s = e ? (valid ? sy : sx) : sx;
        const uint4* row = &KV4[(size_t)s * 32];
        uint4 kr = row[sub];
        uint4 vr = row[16 + sub];
        const __half2* kh = (const __half2*)&kr;
        __half2 t = __hmul2(kh[0], qh0);
        t = __hfma2(kh[1], qh1, t);
        t = __hfma2(kh[2], qh2, t);
        t = __hfma2(kh[3], qh3, t);
        float p = __low2float(t) + __high2float(t);
        p += __shfl_xor_sync(0xffffffffu, p, 1);   // pair = full 16-dim head dot
        float ex = valid ? __expf(p * 0.25f) : 0.f;  // 1/sqrt(HEAD_DIM=16)
        sumex += ex;
        const __half2* vh = (const __half2*)&vr;
#pragma unroll
        for (int j = 0; j < 4; j++) {
            float2 v = __half22float2(vh[j]);
            a[2 * j]     = fmaf(ex, v.x, a[2 * j]);
            a[2 * j + 1] = fmaf(ex, v.y, a[2 * j + 1]);
        }
    };

    int i = 0;
    for (; i + 4 <= deg; i += 4) {
        int4 s = *(const int4*)&idx1[i];
        step2(s.x, s.y, 2);
        step2(s.z, s.w, 2);
    }
    for (; i < deg; i += 2) {
        int sx = idx1[i];
        bool two = (i + 1 < deg);
        int sy = two ? idx1[i + 1] : sx;
        step2(sx, sy, two ? 2 : 1);
    }

    // combine the e=0 / e=1 edge subsets
    sumex += __shfl_xor_sync(0xffffffffu, sumex, 16);
#pragma unroll
    for (int j = 0; j < 8; j++)
        a[j] += __shfl_xor_sync(0xffffffffu, a[j], 16);

    if (e == 0) {
        float w = 1.0f / (sumex + 1e-16f);
        uint4 o;
        o.x = packh2(a[0] * w, a[1] * w);
        o.y = packh2(a[2] * w, a[3] * w);
        o.z = packh2(a[4] * w, a[5] * w);
        o.w = packh2(a[6] * w, a[7] * w);
        *(uint4*)&g_aggh[(size_t)node * 128 + sub * 8] = o;
    }
}

// ---------------- launch ----------------
extern "C" void kernel_launch(void* const* d_in, const int* in_sizes, int n_in,
                              void* d_out, int out_size) {
    const float* q   = (const float*)d_in[0];
    const float* kv  = (const float*)d_in[1];
    const int*   ei  = (const int*)d_in[2];
    const float* W_k = (const float*)d_in[3];
    const float* b_k = (const float*)d_in[4];
    const float* W_v = (const float*)d_in[5];
    const float* b_v = (const float*)d_in[6];
    const float* W_o = (const float*)d_in[7];
    const float* b_o = (const float*)d_in[8];
    float* out = (float*)d_out;

    const int M = NN;
    const int gemmBlocks = (M + 127) / 128;  // 782

    __half *gKV, *gAggh;
    cudaGetSymbolAddress((void**)&gKV, g_KVh);
    cudaGetSymbolAddress((void**)&gAggh, g_aggh);

    // zero the degree histogram
    init_kernel<<<(NN + 255) / 256, 256>>>();

    // single-pass edge binning: count + ELL scatter (atomic slot = rank)
    count_scatter_kernel<<<(EE + 255) / 256, 256>>>(ei);

    // K and V projections -> interleaved KV rows (stride 256: K at +0, V at +128)
    gemm_fused<float, __half><<<gemmBlocks, 256>>>(
        kv, M, 256, W_k, b_k, gKV, W_v, b_v, gKV + 128);

    // per-node attention aggregation (one warp per node, 2 edges/iter)
    node_agg_kernel<<<(NN + 7) / 8, 256>>>(q);

    // output projection: fp16 A (g_aggh) -> fp32 out, single phase
    gemm_fused<__half, float><<<gemmBlocks, 256>>>(
        gAggh, M, 128, W_o, b_o, out, (const float*)nullptr, (const float*)nullptr, (float*)nullptr);
}